// round 3
// baseline (speedup 1.0000x reference)
#include <cuda_runtime.h>

// Problem constants
#define TT   2048      // sequence length T
#define BB   4         // batch
#define HH   16        // heads per batch (E / 64)
#define HD   64        // head dim
#define EE   1024      // embed dim
#define NBH  64        // BB*HH
#define ROWS 16        // query rows per CTA
#define SCH  256       // s-chunk size for K/V smem tiles
#define KTS  260       // padded stride for transposed K/V tile (float4-friendly)

// Scratch for projected q/k/v: [bh][t][d], fp32. ~33.5MB each.
__device__ float g_q[(size_t)NBH * TT * HD];
__device__ float g_k[(size_t)NBH * TT * HD];
__device__ float g_v[(size_t)NBH * TT * HD];

// ---------------------------------------------------------------------------
// Kernel 1: fused QKV projection.
// qkv[t][bh][j] = x[t][b][h*64+d] . W[j][d] + bias[j],  j in [0,192)
// q scaled by 1/8 at write. Output layout [bh][t][d].
// ---------------------------------------------------------------------------
extern "C" __global__ void __launch_bounds__(256)
proj_kernel(const float* __restrict__ x,
            const float* __restrict__ w,
            const float* __restrict__ bias)
{
    extern __shared__ float sm[];
    float* sWT = sm;              // [64][192]  W transposed: sWT[d*192+j]
    float* sX  = sm + 64 * 192;   // [16][64]   x rows for this tile

    const int bh  = blockIdx.x;
    const int t0  = blockIdx.y * 16;
    const int b   = bh >> 4;
    const int h   = bh & 15;
    const int tid = threadIdx.x;

    for (int i = tid; i < 192 * 64; i += 256) {
        int j = i >> 6, d = i & 63;
        sWT[d * 192 + j] = w[i];           // w[j*64+d]
    }
    // 16 rows x 64 d = 1024 floats = 256 float4
    {
        const int t = tid >> 4;            // 0..15
        const int d4 = (tid & 15) * 4;     // 0,4,...,60
        const float4 xv = *(const float4*)&x[(size_t)(t0 + t) * (BB * EE) + (size_t)b * EE + h * HD + d4];
        *(float4*)&sX[t * 64 + d4] = xv;
    }
    __syncthreads();

    const int jg = tid & 63;   // 64 j-groups of 3 -> j = jg*3+u
    const int tg = tid >> 6;   // 4 t-groups of 4  -> t = tg*4+i

    float acc[4][3];
    #pragma unroll
    for (int i = 0; i < 4; i++)
        #pragma unroll
        for (int u = 0; u < 3; u++)
            acc[i][u] = bias[jg * 3 + u];

    #pragma unroll 8
    for (int d = 0; d < 64; d++) {
        float wv[3], xv[4];
        #pragma unroll
        for (int u = 0; u < 3; u++) wv[u] = sWT[d * 192 + jg * 3 + u];
        #pragma unroll
        for (int i = 0; i < 4; i++) xv[i] = sX[(tg * 4 + i) * 64 + d];
        #pragma unroll
        for (int i = 0; i < 4; i++)
            #pragma unroll
            for (int u = 0; u < 3; u++)
                acc[i][u] += xv[i] * wv[u];
    }

    #pragma unroll
    for (int i = 0; i < 4; i++) {
        const int t = t0 + tg * 4 + i;
        const size_t rowbase = ((size_t)bh * TT + t) * HD;
        #pragma unroll
        for (int u = 0; u < 3; u++) {
            const int j = jg * 3 + u;
            const float v = acc[i][u];
            if (j < 64)       g_q[rowbase + j]         = v * 0.125f;  // scaling fused
            else if (j < 128) g_k[rowbase + (j - 64)]  = v;
            else              g_v[rowbase + (j - 128)] = v;
        }
    }
}

// ---------------------------------------------------------------------------
// Helper: load a [SCH][64] chunk of K or V, transposed, into sKT[d][s] (stride KTS).
// float4 global loads; each thread scatters 4 consecutive d of one s.
// ---------------------------------------------------------------------------
__device__ __forceinline__ void load_kv_chunk_T(const float* __restrict__ src,
                                                int s0, float* __restrict__ sKT,
                                                int tid)
{
    // SCH*64 = 16384 floats = 4096 float4; 256 threads -> 16 iters
    #pragma unroll 4
    for (int i = tid; i < SCH * 16; i += 256) {
        const int s  = i >> 4;           // 0..SCH-1
        const int d4 = (i & 15) * 4;     // 0,4,...,60
        const float4 v = *(const float4*)&src[(size_t)(s0 + s) * HD + d4];
        sKT[(d4 + 0) * KTS + s] = v.x;
        sKT[(d4 + 1) * KTS + s] = v.y;
        sKT[(d4 + 2) * KTS + s] = v.z;
        sKT[(d4 + 3) * KTS + s] = v.w;
    }
}

// ---------------------------------------------------------------------------
// Kernel 2: attention + out-projection + averaged weights.
// One CTA per (b, 16-row query tile). Loops all 16 heads:
//   scores (Q.K^T) -> softmax (w held in smem) -> avg_w RMW -> PV -> out-proj.
// avg_w region is exclusively owned by this CTA -> race-free global +=.
// ---------------------------------------------------------------------------
extern "C" __global__ void __launch_bounds__(256)
attn_kernel(const float* __restrict__ outw,
            const float* __restrict__ outb,
            float* __restrict__ out,    // [T][B][E]
            float* __restrict__ avg)    // [B][T][T]
{
    extern __shared__ float sm[];
    float* sS  = sm;                       // [ROWS][TT]  scores -> weights (128KB)
    float* sKT = sS + ROWS * TT;           // [64][KTS]   transposed K/V chunk
    float* sQ  = sKT + 64 * KTS;           // [ROWS][64]
    float* sO  = sQ + ROWS * HD;           // [ROWS][64]

    const int b    = blockIdx.x;
    const int t0   = blockIdx.y * ROWS;
    const int tid  = threadIdx.x;
    const int lane = tid & 31;
    const int wid  = tid >> 5;

    for (int h = 0; h < HH; h++) {
        const int bh = b * HH + h;
        const float* kb = g_k + (size_t)bh * TT * HD;
        const float* vb = g_v + (size_t)bh * TT * HD;

        // Q tile: 16x64 = 256 float4
        {
            const int r  = tid >> 4;
            const int d4 = (tid & 15) * 4;
            const float4 v = *(const float4*)&g_q[((size_t)bh * TT + t0 + r) * HD + d4];
            *(float4*)&sQ[r * 64 + d4] = v;
        }
        __syncthreads();

        // ---------------- scores: sS[r][s] = q_r . k_s ----------------
        {
            const int rg = tid >> 6;   // 0..3 -> rows rg*4..+3
            const int cg = tid & 63;   // 0..63 -> cols cg + {0,64,128,192}
            for (int c = 0; c < TT / SCH; c++) {
                const int s0 = c * SCH;
                load_kv_chunk_T(kb, s0, sKT, tid);
                __syncthreads();
                float acc[4][4];
                #pragma unroll
                for (int i = 0; i < 4; i++)
                    #pragma unroll
                    for (int j = 0; j < 4; j++) acc[i][j] = 0.f;
                #pragma unroll 16
                for (int d = 0; d < 64; d++) {
                    float qv[4], kv[4];
                    #pragma unroll
                    for (int i = 0; i < 4; i++) qv[i] = sQ[(rg * 4 + i) * HD + d];
                    #pragma unroll
                    for (int j = 0; j < 4; j++) kv[j] = sKT[d * KTS + cg + j * 64];
                    #pragma unroll
                    for (int i = 0; i < 4; i++)
                        #pragma unroll
                        for (int j = 0; j < 4; j++)
                            acc[i][j] += qv[i] * kv[j];
                }
                #pragma unroll
                for (int i = 0; i < 4; i++)
                    #pragma unroll
                    for (int j = 0; j < 4; j++)
                        sS[(rg * 4 + i) * TT + s0 + cg + j * 64] = acc[i][j];
                __syncthreads();
            }
        }

        // ---------------- softmax per row + avg_w accumulation ----------------
        {
            #pragma unroll
            for (int rr = 0; rr < ROWS / 8; rr++) {
                const int r = wid + rr * 8;            // each warp owns 2 rows
                float* row = sS + r * TT;
                float m = -1e30f;
                for (int s = lane * 4; s < TT; s += 128) {
                    float4 v = *(float4*)&row[s];
                    m = fmaxf(m, fmaxf(fmaxf(v.x, v.y), fmaxf(v.z, v.w)));
                }
                #pragma unroll
                for (int o = 16; o; o >>= 1) m = fmaxf(m, __shfl_xor_sync(0xffffffffu, m, o));
                float l = 0.f;
                for (int s = lane * 4; s < TT; s += 128) {
                    float4 v = *(float4*)&row[s];
                    v.x = __expf(v.x - m); v.y = __expf(v.y - m);
                    v.z = __expf(v.z - m); v.w = __expf(v.w - m);
                    *(float4*)&row[s] = v;
                    l += v.x + v.y + v.z + v.w;
                }
                #pragma unroll
                for (int o = 16; o; o >>= 1) l += __shfl_xor_sync(0xffffffffu, l, o);
                const float inv = 1.f / l;
                float* ap = avg + ((size_t)b * TT + t0 + r) * TT;
                for (int s = lane * 4; s < TT; s += 128) {
                    float4 v = *(float4*)&row[s];
                    v.x *= inv; v.y *= inv; v.z *= inv; v.w *= inv;
                    *(float4*)&row[s] = v;                 // keep normalized weight for PV
                    float4 a;
                    a.x = v.x * (1.f / HH); a.y = v.y * (1.f / HH);
                    a.z = v.z * (1.f / HH); a.w = v.w * (1.f / HH);
                    if (h) {
                        float4 p = *(float4*)&ap[s];       // race-free: CTA owns this region
                        a.x += p.x; a.y += p.y; a.z += p.z; a.w += p.w;
                    }
                    *(float4*)&ap[s] = a;
                }
            }
            __syncthreads();
        }

        // ---------------- PV: o[r][d] = sum_s w[r][s] * v[s][d] ----------------
        {
            const int sp = tid >> 6;       // 4 s-partitions
            const int g  = tid & 63;
            const int rg = g >> 4;         // rows rg*4..+3
            const int dg = g & 15;         // cols dg*4..+3
            float oacc[4][4];
            #pragma unroll
            for (int i = 0; i < 4; i++)
                #pragma unroll
                for (int j = 0; j < 4; j++) oacc[i][j] = 0.f;

            for (int c = 0; c < TT / SCH; c++) {
                const int s0 = c * SCH;
                load_kv_chunk_T(vb, s0, sKT, tid);
                __syncthreads();
                #pragma unroll 8
                for (int ss = 0; ss < SCH / 4; ss++) {
                    const int s = sp * (SCH / 4) + ss;
                    float wv[4], vv[4];
                    #pragma unroll
                    for (int i = 0; i < 4; i++) wv[i] = sS[(rg * 4 + i) * TT + s0 + s];
                    #pragma unroll
                    for (int j = 0; j < 4; j++) vv[j] = sKT[(dg * 4 + j) * KTS + s];
                    #pragma unroll
                    for (int i = 0; i < 4; i++)
                        #pragma unroll
                        for (int j = 0; j < 4; j++)
                            oacc[i][j] += wv[i] * vv[j];
                }
                __syncthreads();
            }
            // combine the 4 s-partitions into sO
            #pragma unroll
            for (int p = 0; p < 4; p++) {
                if (sp == p) {
                    #pragma unroll
                    for (int i = 0; i < 4; i++)
                        #pragma unroll
                        for (int j = 0; j < 4; j++) {
                            float* o = &sO[(rg * 4 + i) * HD + dg * 4 + j];
                            if (p == 0) *o = oacc[i][j];
                            else        *o += oacc[i][j];
                        }
                }
                __syncthreads();
            }
        }

        // ---------------- out projection for this head ----------------
        {
            const int e  = tid & 63;
            const int rg = tid >> 6;
            float oc[4];
            #pragma unroll
            for (int i = 0; i < 4; i++) oc[i] = outb[e];
            #pragma unroll 8
            for (int d = 0; d < 64; d++) {
                const float wv = outw[e * HD + d];     // 16KB, L1-resident
                #pragma unroll
                for (int i = 0; i < 4; i++)
                    oc[i] += sO[(rg * 4 + i) * HD + d] * wv;
            }
            #pragma unroll
            for (int i = 0; i < 4; i++) {
                const int t = t0 + rg * 4 + i;
                out[((size_t)t * BB + b) * EE + h * HD + e] = oc[i];
            }
        }
        __syncthreads();
    }
}

// ---------------------------------------------------------------------------
extern "C" void kernel_launch(void* const* d_in, const int* in_sizes, int n_in,
                              void* d_out, int out_size)
{
    const float* x    = (const float*)d_in[0];
    const float* w    = (const float*)d_in[1];
    const float* bias = (const float*)d_in[2];
    const float* outw = (const float*)d_in[3];
    const float* outb = (const float*)d_in[4];

    float* out = (float*)d_out;                               // [T][B][E]
    float* avg = out + (size_t)TT * BB * EE;                  // [B][T][T]

    const int SMEM_PROJ = (64 * 192 + 16 * 64) * 4;                    // 53,248 B
    const int SMEM_ATTN = (ROWS * TT + 64 * KTS + 2 * ROWS * HD) * 4;  // ~206KB

    static bool attrs_set = false;
    if (!attrs_set) {
        cudaFuncSetAttribute(proj_kernel, cudaFuncAttributeMaxDynamicSharedMemorySize, SMEM_PROJ);
        cudaFuncSetAttribute(attn_kernel, cudaFuncAttributeMaxDynamicSharedMemorySize, SMEM_ATTN);
        attrs_set = true;
    }

    proj_kernel<<<dim3(NBH, TT / 16), 256, SMEM_PROJ>>>(x, w, bias);
    attn_kernel<<<dim3(BB, TT / ROWS), 256, SMEM_ATTN>>>(outw, outb, out, avg);
}